// round 15
// baseline (speedup 1.0000x reference)
#include <cuda_runtime.h>
#include <cstdint>

// ---------------- problem constants ----------------
#define B_     64
#define BH     32            // batch elements per item (b-half)
#define CIN    32
#define COUT   16
#define HH     64
#define WW     64
#define S_     4096
#define KK     288           // CIN * 3 * 3

#define SLICES 16
#define KSL    (KK / SLICES) // 18, k stride 16: r = slice + 16*k

#define NITEMS (S_ * 2)      // 8192 (s, half) work items
#define NCTA   296           // persistent: 2 CTAs per SM

// one buffer: patch [KK][32f] (parity split-half layout) + weight stripes
#define SP_BYTES (KK * BH * 4)             // 36864
#define SW_BYTES (KK * COUT * 4)           // 18432
#define BUF_BYTES (SP_BYTES + SW_BYTES)    // 55296
#define SMEM_BYTES (2 * BUF_BYTES)         // 110592 -> 2 CTAs/SM

#define PART_ROW_U64 34

// ---------------- device scratch (static, no alloc) ----------------
__device__ float g_Xt[(size_t)HH * WW * CIN * B_];          // 33.55 MB
__device__ float g_tmp[(size_t)NITEMS * 512];               // 16.78 MB
__device__ float g_zero[16];                                // BSS -> zeros

// ---------------- f32x2 helpers ----------------
__device__ __forceinline__ void fma2(unsigned long long& d,
                                     unsigned long long a, unsigned long long b) {
    asm("fma.rn.f32x2 %0, %1, %2, %0;" : "+l"(d) : "l"(a), "l"(b));
}
__device__ __forceinline__ unsigned long long splat2(float x) {
    unsigned long long r;
    asm("mov.b64 %0, {%1, %1};" : "=l"(r) : "f"(x));
    return r;
}
__device__ __forceinline__ unsigned long long add2(unsigned long long a,
                                                   unsigned long long b) {
    unsigned long long r;
    asm("add.rn.f32x2 %0, %1, %2;" : "=l"(r) : "l"(a), "l"(b));
    return r;
}

// ---------------- cp.async helpers ----------------
__device__ __forceinline__ void cpa16(uint32_t dst, const void* src) {
    asm volatile("cp.async.cg.shared.global [%0], [%1], 16;\n"
                 :: "r"(dst), "l"(src));
}
__device__ __forceinline__ void cpa_commit() {
    asm volatile("cp.async.commit_group;\n" ::: "memory");
}
__device__ __forceinline__ void cpa_wait1() {
    asm volatile("cp.async.wait_group 1;\n" ::: "memory");
}
__device__ __forceinline__ void cpa_wait0() {
    asm volatile("cp.async.wait_group 0;\n" ::: "memory");
}

// ---------------------------------------------------------------------------
// Pre-pass: X[b][cin][ih][iw] -> Xt[ih][iw][cin][b]  (coalesced both sides)
// ---------------------------------------------------------------------------
__global__ void __launch_bounds__(256) transpose_kernel(const float* __restrict__ X) {
    __shared__ float tile[64][65];
    const int cin = blockIdx.x >> 6;
    const int ih  = blockIdx.x & 63;
    const int t   = threadIdx.x;
    {
        const int iw = t & 63;
        const int bg = t >> 6;
        const float* src = X + (size_t)cin * (HH * WW) + (size_t)ih * WW;
        #pragma unroll
        for (int r = 0; r < 16; ++r) {
            const int b = bg * 16 + r;
            tile[iw][b] = src[(size_t)b * (CIN * HH * WW) + iw];
        }
    }
    __syncthreads();
    {
        const int b  = t & 63;
        const int wg = t >> 6;
        float* dst = g_Xt + ((size_t)ih * WW) * (CIN * B_) + (size_t)cin * B_;
        #pragma unroll
        for (int r = 0; r < 16; ++r) {
            const int iw = wg * 16 + r;
            dst[(size_t)iw * (CIN * B_) + b] = tile[iw][b];
        }
    }
}

// ---------------------------------------------------------------------------
// Stage one item's patch + weights into smem buffer via cp.async (no bias;
// OOB taps copied from g_zero; bias applied in-mainloop via add.f32x2).
// Layouts identical to R12:
//   patch row r (128B): lo pieces in half (r&1), chunk m at slot m^(r&3).
//   weight: row r quarter q at stripe ((r>>2)*2+(q&1)), slot ((r&3)*2+(q>>1)).
// ---------------------------------------------------------------------------
__device__ __forceinline__ void stage_item(uint32_t buf_smem, int item,
                                           const float* __restrict__ Wt,
                                           int tid) {
    const int s    = item >> 1;
    const int half = item & 1;
    const int oh   = s >> 6;
    const int ow   = s & 63;

    // weights: 1152 float4, 9 per thread
    {
        const float4* gw = (const float4*)(Wt + (size_t)s * (KK * COUT));
        const uint32_t swb = buf_smem + SP_BYTES;
        #pragma unroll
        for (int i = tid; i < (KK * COUT) / 4; i += 128) {
            const int stripe = i >> 3;
            const int slot   = i & 7;
            const int k      = (stripe >> 1) * 4 + (slot >> 1);
            const int q      = ((slot & 1) << 1) + (stripe & 1);
            cpa16(swb + (uint32_t)(stripe * 8 + slot) * 16, gw + k * 4 + q);
        }
    }
    // patch: 9 taps x 256 float4, 2 per thread per tap
    #pragma unroll
    for (int ij = 0; ij < 9; ++ij) {
        const int ih = oh + ij / 3 - 1;
        const int iw = ow + ij % 3 - 1;
        const bool valid = ((unsigned)ih < (unsigned)HH) && ((unsigned)iw < (unsigned)WW);
        const float4* src = (const float4*)(g_Xt + (size_t)(valid ? (ih * WW + iw) : 0) * (CIN * B_));
        #pragma unroll
        for (int t = tid; t < (CIN * BH) / 4; t += 128) {
            const int cin = t >> 3;
            const int q   = t & 7;
            const int r   = cin * 9 + ij;
            const int pos = (q & 1) ^ (r & 1);
            const uint32_t dst = buf_smem
                + (uint32_t)(r * 8 + pos * 4 + ((q >> 1) ^ (r & 3))) * 16;
            const void* sp = valid ? (const void*)(src + cin * 16 + half * 8 + q)
                                   : (const void*)g_zero;
            cpa16(dst, sp);
        }
    }
}

// ---------------------------------------------------------------------------
// Persistent main kernel: 296 CTAs x 128 threads; each CTA loops over items
// item = blockIdx.x + 296*i, double-buffering cp.async staging of item i+1
// behind the compute of item i.
// ---------------------------------------------------------------------------
__global__ void __launch_bounds__(128) lc_kernel(const float* __restrict__ Wt,
                                                 const float* __restrict__ bias,
                                                 float* __restrict__ unused) {
    extern __shared__ float sm[];
    const uint32_t smem0 = (uint32_t)__cvta_generic_to_shared(sm);
    const int tid = threadIdx.x;

    // thread mapping (constant across items)
    const int slice = tid >> 3;
    const int idx   = tid & 7;
    const int bg    = idx >> 1;
    const int cg    = idx & 1;
    const int s3    = slice & 3;
    const int lo_off = ((slice & 1) << 6) + ((bg ^ s3) << 4);
    const int p0_off = slice * 128 + lo_off;
    const int p1_off = slice * 128 + (lo_off ^ 64);
    const int w_off  = SP_BYTES + ((slice >> 2) << 8) + (((s3 << 1) + cg) << 4);

    // prologue: stage first item into buffer 0
    stage_item(smem0, blockIdx.x, Wt, tid);
    cpa_commit();

    int buf = 0;
    for (int item = blockIdx.x; item < NITEMS; item += NCTA, buf ^= 1) {
        const uint32_t cbuf = smem0 + (uint32_t)buf * BUF_BYTES;

        // stage next item into the other buffer (overlaps this item's compute)
        const int nxt = item + NCTA;
        if (nxt < NITEMS) {
            stage_item(smem0 + (uint32_t)(buf ^ 1) * BUF_BYTES, nxt, Wt, tid);
            cpa_commit();
            cpa_wait1();     // current item's group complete (next still pending)
        } else {
            cpa_wait0();
        }
        __syncthreads();

        const int s = item >> 1;
        const unsigned long long bs2 = splat2(bias[s]);

        const char* pbase0 = (const char*)sm + buf * BUF_BYTES + p0_off;
        const char* pbase1 = (const char*)sm + buf * BUF_BYTES + p1_off;
        const char* wbase  = (const char*)sm + buf * BUF_BYTES + w_off;

        unsigned long long acc[4][8];
        #pragma unroll
        for (int i = 0; i < 4; ++i)
            #pragma unroll
            for (int j = 0; j < 8; ++j) acc[i][j] = 0ull;

        #pragma unroll 6
        for (int k = 0; k < KSL; ++k) {
            const ulonglong2 u0 = *(const ulonglong2*)(pbase0 + k * 2048);
            const ulonglong2 u1 = *(const ulonglong2*)(pbase1 + k * 2048);
            const float4 wlo = *(const float4*)(wbase + k * 1024);
            const float4 whi = *(const float4*)(wbase + k * 1024 + 128);

            const unsigned long long p[4] = {
                add2(u0.x, bs2), add2(u0.y, bs2),
                add2(u1.x, bs2), add2(u1.y, bs2)
            };
            const unsigned long long w2[8] = {
                splat2(wlo.x), splat2(wlo.y), splat2(wlo.z), splat2(wlo.w),
                splat2(whi.x), splat2(whi.y), splat2(whi.z), splat2(whi.w)
            };
            #pragma unroll
            for (int i = 0; i < 4; ++i)
                #pragma unroll
                for (int j = 0; j < 8; ++j)
                    fma2(acc[i][j], p[i], w2[j]);
        }

        // reduce 16 slices: shfl pair (dist 16) -> 8 partials via smem
        #pragma unroll
        for (int i = 0; i < 4; ++i)
            #pragma unroll
            for (int j = 0; j < 8; ++j) {
                unsigned long long o = __shfl_down_sync(0xffffffffu, acc[i][j], 16);
                acc[i][j] = add2(acc[i][j], o);
            }

        __syncthreads();   // all mainloop smem reads done
        unsigned long long* part = (unsigned long long*)((char*)sm + buf * BUF_BYTES);
        const int lane = tid & 31;
        const int wrp  = tid >> 5;
        if (lane < 16) {
            ulonglong2* pr = (ulonglong2*)(part + (size_t)(wrp * 16 + lane) * PART_ROW_U64);
            #pragma unroll
            for (int i = 0; i < 4; ++i)
                #pragma unroll
                for (int j = 0; j < 8; j += 2) {
                    ulonglong2 v; v.x = acc[i][j]; v.y = acc[i][j + 1];
                    pr[(i * 8 + j) >> 1] = v;
                }
        }
        __syncthreads();

        // final 8-way sum; thread t -> E = 2t, 2t+1; contiguous store
        {
            float res[4];
            #pragma unroll
            for (int e = 0; e < 2; ++e) {
                const int E  = tid * 2 + e;
                const int bp = E & 15;
                const int c  = E >> 4;
                const int ix = ((bp >> 2) << 1) + (c >> 3);
                const int a  = ((bp & 3) << 3) + (c & 7);
                unsigned long long sum = part[(size_t)ix * PART_ROW_U64 + a];
                #pragma unroll
                for (int m = 1; m < 8; ++m)
                    sum = add2(sum, part[(size_t)(ix + 8 * m) * PART_ROW_U64 + a]);
                asm("mov.b64 {%0, %1}, %2;"
                    : "=f"(res[2 * e]), "=f"(res[2 * e + 1]) : "l"(sum));
            }
            float4* o = (float4*)(g_tmp + (size_t)item * 512 + tid * 4);
            *o = make_float4(res[0], res[1], res[2], res[3]);
        }
        __syncthreads();   // scratch reads done before next stage targets this buf
    }
}

// ---------------------------------------------------------------------------
// Epilogue: g_tmp[(s*2+half)*512 + (c*16+bp)*2 + b0] -> out[(b*16+c)*S + s]
// ---------------------------------------------------------------------------
#define EP_PITCH 516
#define EP_SMEM  (32 * EP_PITCH * 4)   // 66048

__global__ void __launch_bounds__(256) epi_kernel(float* __restrict__ out) {
    extern __shared__ float es[];
    const int tid = threadIdx.x;
    const int s0  = blockIdx.x * 16;

    const float4* src = (const float4*)(g_tmp + (size_t)(s0 * 2) * 512);
    #pragma unroll
    for (int t = tid; t < 32 * 128; t += 256) {
        const int row = t >> 7;
        ((float4*)(es + (size_t)row * EP_PITCH))[t & 127] = src[t];
    }
    __syncthreads();

    const int p  = tid >> 1;
    const int hs = tid & 1;
    #pragma unroll
    for (int rr = 0; rr < 8; ++rr) {
        const int R  = p + 128 * rr;          // b*16 + c
        const int b  = R >> 4;
        const int c  = R & 15;
        const int h  = b >> 5;
        const int bp = (b >> 1) & 15;
        const int b0 = b & 1;
        const int col = ((c << 4) + bp) * 2 + b0;
        float v[8];
        #pragma unroll
        for (int z = 0; z < 8; ++z) {
            const int sl = hs * 8 + z;
            v[z] = es[(size_t)(sl * 2 + h) * EP_PITCH + col];
        }
        float4* o = (float4*)(out + (size_t)R * S_ + s0 + hs * 8);
        o[0] = make_float4(v[0], v[1], v[2], v[3]);
        o[1] = make_float4(v[4], v[5], v[6], v[7]);
    }
}

// ---------------------------------------------------------------------------
extern "C" void kernel_launch(void* const* d_in, const int* in_sizes, int n_in,
                              void* d_out, int out_size) {
    const float* X  = nullptr;   // 8388608
    const float* Wt = nullptr;   // 18874368
    const float* Bp = nullptr;   // 4096
    for (int i = 0; i < n_in; ++i) {
        if      (in_sizes[i] == B_ * CIN * HH * WW) X  = (const float*)d_in[i];
        else if (in_sizes[i] == S_ * KK * COUT)     Wt = (const float*)d_in[i];
        else if (in_sizes[i] == S_)                 Bp = (const float*)d_in[i];
    }

    cudaFuncSetAttribute(lc_kernel,  cudaFuncAttributeMaxDynamicSharedMemorySize, SMEM_BYTES);
    cudaFuncSetAttribute(epi_kernel, cudaFuncAttributeMaxDynamicSharedMemorySize, EP_SMEM);

    transpose_kernel<<<CIN * HH, 256>>>(X);
    lc_kernel<<<NCTA, 128, SMEM_BYTES>>>(Wt, Bp, (float*)d_out);
    epi_kernel<<<S_ / 16, 256, EP_SMEM>>>((float*)d_out);
}

// round 17
// speedup vs baseline: 1.8802x; 1.8802x over previous
#include <cuda_runtime.h>
#include <cstdint>

// ---------------- problem constants ----------------
#define B_     64
#define BH     32            // batch elements per CTA (b-half)
#define CIN    32
#define COUT   16
#define HH     64
#define WW     64
#define S_     4096
#define KK     288           // CIN * 3 * 3

#define SLICES 16
#define KSL    (KK / SLICES) // 18, k stride 16: r = slice + 16*k

// smem: patch ONLY — [KK][32f] 128B rows, chunk-XOR swizzle (R10 layout)
#define SMEM_BYTES (KK * BH * 4)   // 36864 -> 5 CTAs/SM (with 102-reg cap)

// reduction scratch (reuses patch region): 64 rows x 34 u64 (272B rows)
#define PART_ROW_U64 34

// ---------------- device scratch (static, no alloc) ----------------
__device__ float g_Xt[(size_t)HH * WW * CIN * B_];          // 33.55 MB
__device__ float g_tmp[(size_t)S_ * 2 * 512];               // 16.78 MB

// ---------------- f32x2 helpers ----------------
__device__ __forceinline__ void fma2(unsigned long long& d,
                                     unsigned long long a, unsigned long long b) {
    asm("fma.rn.f32x2 %0, %1, %2, %0;" : "+l"(d) : "l"(a), "l"(b));
}
__device__ __forceinline__ unsigned long long splat2(float x) {
    unsigned long long r;
    asm("mov.b64 %0, {%1, %1};" : "=l"(r) : "f"(x));
    return r;
}
__device__ __forceinline__ unsigned long long add2(unsigned long long a,
                                                   unsigned long long b) {
    unsigned long long r;
    asm("add.rn.f32x2 %0, %1, %2;" : "=l"(r) : "l"(a), "l"(b));
    return r;
}

// ---------------------------------------------------------------------------
// Pre-pass: X[b][cin][ih][iw] -> Xt[ih][iw][cin][b]  (coalesced both sides)
// ---------------------------------------------------------------------------
__global__ void __launch_bounds__(256) transpose_kernel(const float* __restrict__ X) {
    __shared__ float tile[64][65];
    const int cin = blockIdx.x >> 6;
    const int ih  = blockIdx.x & 63;
    const int t   = threadIdx.x;
    {
        const int iw = t & 63;
        const int bg = t >> 6;
        const float* src = X + (size_t)cin * (HH * WW) + (size_t)ih * WW;
        #pragma unroll
        for (int r = 0; r < 16; ++r) {
            const int b = bg * 16 + r;
            tile[iw][b] = src[(size_t)b * (CIN * HH * WW) + iw];
        }
    }
    __syncthreads();
    {
        const int b  = t & 63;
        const int wg = t >> 6;
        float* dst = g_Xt + ((size_t)ih * WW) * (CIN * B_) + (size_t)cin * B_;
        #pragma unroll
        for (int r = 0; r < 16; ++r) {
            const int iw = wg * 16 + r;
            dst[(size_t)iw * (CIN * B_) + b] = tile[iw][b];
        }
    }
}

// ---------------------------------------------------------------------------
// Main kernel: 128 threads, one CTA per (s, b-half). R10 structure, BUT:
//   - weights are NOT staged in smem: each thread streams its 32B/k weight
//     operands from global with an explicit distance-2 register prefetch
//     (the load for step k+2 issues before step k's FMAs), so the ~260cyc
//     L2 latency is covered by ~2 iterations x 5 warps of issue traffic.
//   - smem holds only the patch (36.9KB) -> 5 CTAs/SM (20 warps).
// Thread map: slice = tid>>3 (0..15), idx = tid&7, bg = idx>>1, cg = idx&1.
// Thread k-sequence: r = slice + 16*k -> r&3 const/thread; all addresses
//   are base + k*const.
// Patch rows 128B (R10 layout): 32B chunk m at slot m ^ (r&3); u0/u1 read
//   the lo/hi 16B of the thread's chunk.
// ---------------------------------------------------------------------------
__global__ void __launch_bounds__(128, 5) lc_kernel(const float* __restrict__ Wt,
                                                    const float* __restrict__ bias,
                                                    float* __restrict__ unused) {
    extern __shared__ float sm[];
    float4* sp4 = (float4*)sm;                               // patch, KK*8 float4

    const int bid  = blockIdx.x;
    const int s    = bid >> 1;
    const int half = bid & 1;
    const int oh   = s >> 6;
    const int ow   = s & 63;
    const int tid  = threadIdx.x;
    const float bs = bias[s];

    // ---- stage patch: 9 taps x 256 float4; bias pre-added, OOB = bias ----
    #pragma unroll
    for (int ij = 0; ij < 9; ++ij) {
        const int ih = oh + ij / 3 - 1;
        const int iw = ow + ij % 3 - 1;
        const bool valid = ((unsigned)ih < (unsigned)HH) && ((unsigned)iw < (unsigned)WW);
        const float4* src = (const float4*)(g_Xt + (size_t)(valid ? (ih * WW + iw) : 0) * (CIN * B_));
        #pragma unroll
        for (int t = tid; t < (CIN * BH) / 4; t += 128) {    // 256 float4
            const int cin = t >> 3;
            const int q   = t & 7;           // chunk q>>1, piece q&1
            float4 v = valid ? src[cin * 16 + half * 8 + q]
                             : make_float4(0.f, 0.f, 0.f, 0.f);
            v.x += bs; v.y += bs; v.z += bs; v.w += bs;
            const int r = cin * 9 + ij;
            sp4[r * 8 + (((q >> 1) ^ (r & 3)) << 1) + (q & 1)] = v;
        }
    }
    __syncthreads();

    // ---- mainloop: 18 strided k-steps, 8b x 8c per thread ----
    const int slice = tid >> 3;          // 0..15
    const int idx   = tid & 7;
    const int bg    = idx >> 1;          // 0..3
    const int cg    = idx & 1;
    const int s3    = slice & 3;

    const char*  pbase = (const char*)sm + slice * 128 + ((bg ^ s3) << 5);
    const float* wptr  = Wt + (size_t)s * (KK * COUT) + slice * COUT + cg * 8;
    // per-k weight stride: 16 rows * 16 floats = 256 floats

    unsigned long long acc[4][8];
    #pragma unroll
    for (int i = 0; i < 4; ++i)
        #pragma unroll
        for (int j = 0; j < 8; ++j) acc[i][j] = 0ull;

    // distance-2 register prefetch pipeline for weights
    float4 wlo[2], whi[2];
    wlo[0] = *(const float4*)(wptr);
    whi[0] = *(const float4*)(wptr + 4);
    wlo[1] = *(const float4*)(wptr + 256);
    whi[1] = *(const float4*)(wptr + 256 + 4);

    #pragma unroll
    for (int k = 0; k < KSL; ++k) {
        const float4 cl = wlo[k & 1];
        const float4 ch = whi[k & 1];
        if (k < KSL - 2) {                       // issue k+2 load NOW (overlaps FMAs)
            wlo[k & 1] = *(const float4*)(wptr + (k + 2) * 256);
            whi[k & 1] = *(const float4*)(wptr + (k + 2) * 256 + 4);
        }

        const ulonglong2 u0 = *(const ulonglong2*)(pbase + k * 2048);        // b 8bg..+3
        const ulonglong2 u1 = *(const ulonglong2*)(pbase + k * 2048 + 16);   // b 8bg+4..+7

        const unsigned long long p[4] = { u0.x, u0.y, u1.x, u1.y };
        const unsigned long long w2[8] = {
            splat2(cl.x), splat2(cl.y), splat2(cl.z), splat2(cl.w),
            splat2(ch.x), splat2(ch.y), splat2(ch.z), splat2(ch.w)
        };
        #pragma unroll
        for (int i = 0; i < 4; ++i)
            #pragma unroll
            for (int j = 0; j < 8; ++j)
                fma2(acc[i][j], p[i], w2[j]);
    }

    // ---- reduce 16 slices: shfl pair (dist 16) -> 8 partials via smem ----
    #pragma unroll
    for (int i = 0; i < 4; ++i)
        #pragma unroll
        for (int j = 0; j < 8; ++j) {
            unsigned long long o = __shfl_down_sync(0xffffffffu, acc[i][j], 16);
            acc[i][j] = add2(acc[i][j], o);
        }

    __syncthreads();   // done reading patch smem
    unsigned long long* part = (unsigned long long*)sm;      // [64][34] u64
    const int lane = tid & 31;
    const int wrp  = tid >> 5;
    if (lane < 16) {
        ulonglong2* pr = (ulonglong2*)(part + (size_t)(wrp * 16 + lane) * PART_ROW_U64);
        #pragma unroll
        for (int i = 0; i < 4; ++i)
            #pragma unroll
            for (int j = 0; j < 8; j += 2) {
                ulonglong2 v; v.x = acc[i][j]; v.y = acc[i][j + 1];
                pr[(i * 8 + j) >> 1] = v;
            }
    }
    __syncthreads();

    // ---- final 8-way sum; thread t -> E = 2t, 2t+1; contiguous store ----
    {
        float res[4];
        #pragma unroll
        for (int e = 0; e < 2; ++e) {
            const int E  = tid * 2 + e;
            const int bp = E & 15;
            const int c  = E >> 4;
            const int ix = ((bp >> 2) << 1) + (c >> 3);      // bg*2+cg
            const int a  = ((bp & 3) << 3) + (c & 7);        // i*8+j
            unsigned long long sum = part[(size_t)ix * PART_ROW_U64 + a];
            #pragma unroll
            for (int m = 1; m < 8; ++m)
                sum = add2(sum, part[(size_t)(ix + 8 * m) * PART_ROW_U64 + a]);
            asm("mov.b64 {%0, %1}, %2;" : "=f"(res[2 * e]), "=f"(res[2 * e + 1]) : "l"(sum));
        }
        float4* o = (float4*)(g_tmp + (size_t)bid * 512 + tid * 4);
        *o = make_float4(res[0], res[1], res[2], res[3]);
    }
}

// ---------------------------------------------------------------------------
// Epilogue: g_tmp[(s*2+half)*512 + (c*16+bp)*2 + b0] -> out[(b*16+c)*S + s]
// CTA = 16 s-values x all 1024 (b,c) rows through a 66KB smem tile.
// ---------------------------------------------------------------------------
#define EP_PITCH 516
#define EP_SMEM  (32 * EP_PITCH * 4)   // 66048

__global__ void __launch_bounds__(256) epi_kernel(float* __restrict__ out) {
    extern __shared__ float es[];
    const int tid = threadIdx.x;
    const int s0  = blockIdx.x * 16;

    const float4* src = (const float4*)(g_tmp + (size_t)(s0 * 2) * 512);
    #pragma unroll
    for (int t = tid; t < 32 * 128; t += 256) {
        const int row = t >> 7;
        ((float4*)(es + (size_t)row * EP_PITCH))[t & 127] = src[t];
    }
    __syncthreads();

    const int p  = tid >> 1;
    const int hs = tid & 1;
    #pragma unroll
    for (int rr = 0; rr < 8; ++rr) {
        const int R  = p + 128 * rr;          // b*16 + c
        const int b  = R >> 4;
        const int c  = R & 15;
        const int h  = b >> 5;
        const int bp = (b >> 1) & 15;
        const int b0 = b & 1;
        const int col = ((c << 4) + bp) * 2 + b0;
        float v[8];
        #pragma unroll
        for (int z = 0; z < 8; ++z) {
            const int sl = hs * 8 + z;
            v[z] = es[(size_t)(sl * 2 + h) * EP_PITCH + col];
        }
        float4* o = (float4*)(out + (size_t)R * S_ + s0 + hs * 8);
        o[0] = make_float4(v[0], v[1], v[2], v[3]);
        o[1] = make_float4(v[4], v[5], v[6], v[7]);
    }
}

// ---------------------------------------------------------------------------
extern "C" void kernel_launch(void* const* d_in, const int* in_sizes, int n_in,
                              void* d_out, int out_size) {
    const float* X  = nullptr;   // 8388608
    const float* Wt = nullptr;   // 18874368
    const float* Bp = nullptr;   // 4096
    for (int i = 0; i < n_in; ++i) {
        if      (in_sizes[i] == B_ * CIN * HH * WW) X  = (const float*)d_in[i];
        else if (in_sizes[i] == S_ * KK * COUT)     Wt = (const float*)d_in[i];
        else if (in_sizes[i] == S_)                 Bp = (const float*)d_in[i];
    }

    cudaFuncSetAttribute(lc_kernel,  cudaFuncAttributeMaxDynamicSharedMemorySize, SMEM_BYTES);
    cudaFuncSetAttribute(epi_kernel, cudaFuncAttributeMaxDynamicSharedMemorySize, EP_SMEM);

    transpose_kernel<<<CIN * HH, 256>>>(X);
    lc_kernel<<<S_ * 2, 128, SMEM_BYTES>>>(Wt, Bp, (float*)d_out);
    epi_kernel<<<S_ / 16, 256, EP_SMEM>>>((float*)d_out);
}